// round 1
// baseline (speedup 1.0000x reference)
#include <cuda_runtime.h>
#include <cuda_bf16.h>

// SoftAttention collapsed form:
//   adj[i][j] = s_send[i] + s_rec[j] + bias  ->  softmax over j cancels the
//   per-row constant, so every output row of a batch equals
//   sum_j softmax(hs[j]. w[H:2H])[j] * hs[j].
//
// Shapes: B*N = 400 batches, T = 64 rows, H = 32 features.
// One CTA per batch, 128 threads.

#define T_DIM 64
#define H_DIM 32
#define PITCH 33            // conflict-free for row-major dots AND column sums
#define BATCH_ELEMS (T_DIM * H_DIM)   // 2048

__global__ __launch_bounds__(128, 8)
void soft_attention_kernel(const float* __restrict__ x,
                           const float* __restrict__ w,
                           float* __restrict__ out) {
    __shared__ float hs[T_DIM * PITCH];  // 64 x 32, pitch 33
    __shared__ float ws[H_DIM];          // w[32..63]
    __shared__ float p[T_DIM];           // scores -> probs
    __shared__ float ov[H_DIM];          // output vector

    const int b   = blockIdx.x;
    const int tid = threadIdx.x;
    const float* xb = x + (size_t)b * BATCH_ELEMS;

    // --- load tile: 2048 floats, float4-coalesced (512 float4 / 128 thr = 4 ea)
#pragma unroll
    for (int i = 0; i < 4; i++) {
        int e = (tid + i * 128) * 4;          // element offset, multiple of 4
        float4 v = *reinterpret_cast<const float4*>(xb + e);
        int row = e >> 5;                     // /32
        int col = e & 31;
        float* d = hs + row * PITCH + col;
        d[0] = v.x; d[1] = v.y; d[2] = v.z; d[3] = v.w;
    }
    if (tid < H_DIM) ws[tid] = w[H_DIM + tid];   // only w[H:2H] matters
    __syncthreads();

    // --- per-row score s[j] = hs[j] . w2   (threads 0..63)
    if (tid < T_DIM) {
        float acc = 0.f;
#pragma unroll
        for (int k = 0; k < H_DIM; k++)
            acc = fmaf(hs[tid * PITCH + k], ws[k], acc);
        p[tid] = acc;
    }
    __syncthreads();

    // --- softmax over 64 values (warp 0, shfl reductions)
    if (tid < 32) {
        float a = p[tid], c = p[tid + 32];
        float m = fmaxf(a, c);
#pragma unroll
        for (int o = 16; o; o >>= 1)
            m = fmaxf(m, __shfl_xor_sync(0xffffffff, m, o));
        float e0 = __expf(a - m), e1 = __expf(c - m);
        float s = e0 + e1;
#pragma unroll
        for (int o = 16; o; o >>= 1)
            s += __shfl_xor_sync(0xffffffff, s, o);
        float inv = 1.f / s;
        p[tid]      = e0 * inv;
        p[tid + 32] = e1 * inv;
    }
    __syncthreads();

    // --- output vector ov[h] = sum_j p[j] * hs[j][h]  (threads 0..31)
    // pitch-33 => hs[j*33 + h]: banks (j+h)%32, conflict-free across lanes.
    if (tid < H_DIM) {
        float acc = 0.f;
#pragma unroll
        for (int j = 0; j < T_DIM; j++)
            acc = fmaf(p[j], hs[j * PITCH + tid], acc);
        ov[tid] = acc;
    }
    __syncthreads();

    // --- broadcast-write: every row of the 64x32 output = ov
    float* ob = out + (size_t)b * BATCH_ELEMS;
#pragma unroll
    for (int i = 0; i < 4; i++) {
        int e   = (tid + i * 128) * 4;
        int col = e & 31;                 // 32 % 4 == 0 -> col..col+3 same row
        float4 v = make_float4(ov[col], ov[col + 1], ov[col + 2], ov[col + 3]);
        *reinterpret_cast<float4*>(ob + e) = v;
    }
}

extern "C" void kernel_launch(void* const* d_in, const int* in_sizes, int n_in,
                              void* d_out, int out_size) {
    // metadata order: inputs, rel_rec_t, rel_send_t, soft_att_w, soft_att_b
    const float* x = (const float*)d_in[0];
    const float* w = (const float*)d_in[3];
    float* out = (float*)d_out;

    const int batches = 8 * 50;  // B * N = 400
    soft_attention_kernel<<<batches, 128>>>(x, w, out);
}

// round 2
// speedup vs baseline: 1.0386x; 1.0386x over previous
#include <cuda_runtime.h>
#include <cuda_bf16.h>

// SoftAttention collapsed form (see R1): for each of the 400 (B*N) batches,
// every output row equals sum_j softmax_j(hs[j] . w[H:2H]) * hs[j].
//
// R2: one warp per batch, register-resident tile, no smem, no barriers.
// Lane layout: lane l owns rows {4i + (l>>3) : i=0..15}, cols (l&7)*4..+3.
//   - row dot     -> shfl xor {1,2,4}   (within 8-lane col groups)
//   - softmax sum -> shfl xor {8,16}    (across the 4 row subgroups)
//   - out reduce  -> shfl xor {8,16}

#define T_DIM 64
#define H_DIM 32
#define BATCH_ELEMS (T_DIM * H_DIM)   // 2048

__global__ __launch_bounds__(32, 16)
void soft_attention_kernel(const float* __restrict__ x,
                           const float* __restrict__ w,
                           float* __restrict__ out) {
    const int lane = threadIdx.x & 31;
    const int b    = blockIdx.x;

    const int g  = lane >> 3;        // row subgroup 0..3
    const int c4 = (lane & 7) * 4;   // column base

    const float* xb = x + (size_t)b * BATCH_ELEMS;

    // w2 fragment for this lane's columns (only w[H:2H] matters)
    const float4 wv = *reinterpret_cast<const float4*>(w + H_DIM + c4);

    // ---- load tile: 16 independent LDG.128, front-batched (MLP=16)
    float4 v[16];
#pragma unroll
    for (int i = 0; i < 16; i++)
        v[i] = *reinterpret_cast<const float4*>(xb + (4 * i + g) * H_DIM + c4);

    // ---- per-row scores: partial dot (4 FMA) + reduce over 8-lane col group
    float s[16];
#pragma unroll
    for (int i = 0; i < 16; i++) {
        float d = fmaf(v[i].x, wv.x,
                  fmaf(v[i].y, wv.y,
                  fmaf(v[i].z, wv.z, v[i].w * wv.w)));
        d += __shfl_xor_sync(0xffffffffu, d, 1);
        d += __shfl_xor_sync(0xffffffffu, d, 2);
        d += __shfl_xor_sync(0xffffffffu, d, 4);
        s[i] = d;   // = score of row 4i+g, replicated across the 8-lane group
    }

    // ---- softmax over 64 scores
    float m = s[0];
#pragma unroll
    for (int i = 1; i < 16; i++) m = fmaxf(m, s[i]);
    // full-warp max (replicated values don't affect max)
#pragma unroll
    for (int o = 16; o; o >>= 1)
        m = fmaxf(m, __shfl_xor_sync(0xffffffffu, m, o));

    float lsum = 0.f;
#pragma unroll
    for (int i = 0; i < 16; i++) {
        s[i] = __expf(s[i] - m);
        lsum += s[i];
    }
    // row sets depend only on g=lane>>3 -> distinct across xor 8,16 only
    lsum += __shfl_xor_sync(0xffffffffu, lsum, 8);
    lsum += __shfl_xor_sync(0xffffffffu, lsum, 16);
    const float inv = 1.f / lsum;

    // ---- output vector: acc[c4..c4+3] = sum_j p[j] * hs[j][c4..c4+3]
    float4 acc = make_float4(0.f, 0.f, 0.f, 0.f);
#pragma unroll
    for (int i = 0; i < 16; i++) {
        const float pi = s[i] * inv;
        acc.x = fmaf(pi, v[i].x, acc.x);
        acc.y = fmaf(pi, v[i].y, acc.y);
        acc.z = fmaf(pi, v[i].z, acc.z);
        acc.w = fmaf(pi, v[i].w, acc.w);
    }
    // reduce across the 4 row subgroups (xor 8, 16)
#pragma unroll
    for (int o = 8; o <= 16; o <<= 1) {
        acc.x += __shfl_xor_sync(0xffffffffu, acc.x, o);
        acc.y += __shfl_xor_sync(0xffffffffu, acc.y, o);
        acc.z += __shfl_xor_sync(0xffffffffu, acc.z, o);
        acc.w += __shfl_xor_sync(0xffffffffu, acc.w, o);
    }

    // ---- broadcast-write: every row of the 64x32 output = acc (per col group)
    float* ob = out + (size_t)b * BATCH_ELEMS;
#pragma unroll
    for (int i = 0; i < 16; i++)
        *reinterpret_cast<float4*>(ob + (4 * i + g) * H_DIM + c4) = acc;
}

extern "C" void kernel_launch(void* const* d_in, const int* in_sizes, int n_in,
                              void* d_out, int out_size) {
    // metadata order: inputs, rel_rec_t, rel_send_t, soft_att_w, soft_att_b
    const float* x = (const float*)d_in[0];
    const float* w = (const float*)d_in[3];
    float* out = (float*)d_out;

    const int batches = 8 * 50;  // B * N = 400
    soft_attention_kernel<<<batches, 32>>>(x, w, out);
}